// round 1
// baseline (speedup 1.0000x reference)
#include <cuda_runtime.h>
#include <cuda_bf16.h>
#include <math.h>

// ---------------- problem constants ----------------
#define NB      4          // batch
#define LQ      4096       // queries
#define DM      256        // d_model
#define NH      8          // heads
#define NL      4          // levels
#define NP      4          // points
#define DH      32         // head dim
#define S_TOT   7680       // sum of level lengths
#define HLP     (NH*NL*NP) // 128

// ---------------- scratch (static device memory; no allocs allowed) ----------
__device__ float g_value[NB * S_TOT * DM];   // (N*S, 256)
__device__ float g_off  [NB * LQ * HLP];     // (N*Lq, 128)
__device__ float g_aw   [NB * LQ * HLP];     // (N*Lq, 128)
__device__ float g_mid  [NB * LQ * DM];      // (N*Lq, 256)

// ---------------- SGEMM: C[M,N] = A[M,K] @ B[K,N] + bias[N] -----------------
// BM=128, BN=128, BK=8, 256 threads, 8x8 per thread. All dims here are exact
// multiples (M in {30720,16384}, N in {128,256}, K=256) so no edge handling.
__global__ __launch_bounds__(256)
void sgemm_bias_kernel(const float* __restrict__ A,
                       const float* __restrict__ B,
                       const float* __restrict__ bias,
                       float* __restrict__ C,
                       int M, int N, int K)
{
    constexpr int BM = 128, BN = 128, BK = 8, TM = 8, TN = 8;
    __shared__ float As[BK][BM];
    __shared__ float Bs[BK][BN];

    const int tid = threadIdx.x;
    const int block_row = blockIdx.y * BM;
    const int block_col = blockIdx.x * BN;

    // A-tile load mapping: 128 rows x 8 k = 256 float4
    const int a_row = tid >> 1;          // 0..127
    const int a_col = (tid & 1) << 2;    // 0 or 4
    // B-tile load mapping: 8 k x 128 cols = 256 float4
    const int b_row = tid >> 5;          // 0..7
    const int b_col = (tid & 31) << 2;   // 0..124

    const int trow = (tid >> 4) * TM;    // 0..120
    const int tcol = (tid & 15) * TN;    // 0..120

    float acc[TM][TN];
    #pragma unroll
    for (int i = 0; i < TM; i++)
        #pragma unroll
        for (int j = 0; j < TN; j++)
            acc[i][j] = 0.0f;

    const float* Aptr = A + (long)(block_row + a_row) * K + a_col;
    const float* Bptr = B + (long)b_row * N + block_col + b_col;

    for (int k0 = 0; k0 < K; k0 += BK) {
        float4 av = *(const float4*)(Aptr + k0);
        As[a_col + 0][a_row] = av.x;
        As[a_col + 1][a_row] = av.y;
        As[a_col + 2][a_row] = av.z;
        As[a_col + 3][a_row] = av.w;
        float4 bv = *(const float4*)(Bptr + (long)k0 * N);
        *(float4*)&Bs[b_row][b_col] = bv;
        __syncthreads();

        #pragma unroll
        for (int kk = 0; kk < BK; kk++) {
            float ar[TM], br[TN];
            #pragma unroll
            for (int i = 0; i < TM; i++) ar[i] = As[kk][trow + i];
            #pragma unroll
            for (int j = 0; j < TN; j++) br[j] = Bs[kk][tcol + j];
            #pragma unroll
            for (int i = 0; i < TM; i++)
                #pragma unroll
                for (int j = 0; j < TN; j++)
                    acc[i][j] = fmaf(ar[i], br[j], acc[i][j]);
        }
        __syncthreads();
    }

    #pragma unroll
    for (int i = 0; i < TM; i++) {
        float* crow = C + (long)(block_row + trow + i) * N + block_col + tcol;
        #pragma unroll
        for (int j = 0; j < TN; j += 4) {
            float4 o;
            o.x = acc[i][j + 0] + bias[block_col + tcol + j + 0];
            o.y = acc[i][j + 1] + bias[block_col + tcol + j + 1];
            o.z = acc[i][j + 2] + bias[block_col + tcol + j + 2];
            o.w = acc[i][j + 3] + bias[block_col + tcol + j + 3];
            *(float4*)(crow + j) = o;
        }
    }
}

// ---------------- sampling kernel -------------------------------------------
// One block per (n,q) pair: 256 threads = 8 warps, warp m handles head m.
// Lanes 0..15 (duplicated in 16..31) each own one (level,point); softmax over
// 16 via width-16 shuffles; then 16-iteration loop where lane = channel dim
// for coalesced 128B gathers from g_value (31.5MB -> resident in L2).
__global__ __launch_bounds__(256)
void msda_sample_kernel(const float* __restrict__ ref,     // (N,Lq,4)
                        const int*   __restrict__ shapes,  // (4)
                        const int*   __restrict__ start)   // (4)
{
    const int nq   = blockIdx.x;        // 0 .. N*Lq-1
    const int n    = nq / LQ;
    const int m    = threadIdx.x >> 5;  // head
    const int lane = threadIdx.x & 31;
    const int lp   = lane & 15;         // (level,point) index
    const int l    = lp >> 2;

    const int   Ti = shapes[l];
    const float Tf = (float)Ti;
    const int   st = start[l];

    const float offv  = g_off[(long)nq * HLP + m * 16 + lp];
    const float logit = g_aw [(long)nq * HLP + m * 16 + lp];
    const float r     = ref[(long)nq * NL + l];

    // sampling position
    float x  = fminf(fmaxf(r * Tf + offv - 0.5f, 0.0f), Tf - 1.0f);
    float x0 = floorf(x);
    float w  = x - x0;
    int   i0 = (int)x0;
    int   i1 = min(i0 + 1, Ti - 1);
    int   g0 = (n * S_TOT + st + i0) * DM + m * DH;
    int   g1 = (n * S_TOT + st + i1) * DM + m * DH;

    // softmax over 16 (lanes duplicated pairwise; width-16 butterflies)
    float mx = logit;
    #pragma unroll
    for (int o = 8; o > 0; o >>= 1)
        mx = fmaxf(mx, __shfl_xor_sync(0xffffffffu, mx, o, 16));
    float e = expf(logit - mx);
    float ssum = e;
    #pragma unroll
    for (int o = 8; o > 0; o >>= 1)
        ssum += __shfl_xor_sync(0xffffffffu, ssum, o, 16);
    float aw = e / ssum;

    // gather + lerp + weighted accumulation; lane = channel
    float acc = 0.0f;
    #pragma unroll
    for (int p = 0; p < 16; p++) {
        int   gg0 = __shfl_sync(0xffffffffu, g0, p);
        int   gg1 = __shfl_sync(0xffffffffu, g1, p);
        float ww  = __shfl_sync(0xffffffffu, w,  p);
        float aa  = __shfl_sync(0xffffffffu, aw, p);
        float v0 = g_value[gg0 + lane];
        float v1 = g_value[gg1 + lane];
        acc = fmaf(aa, fmaf(ww, v1 - v0, v0), acc);
    }

    g_mid[(long)nq * DM + m * DH + lane] = acc;
}

// ---------------- launch ------------------------------------------------------
extern "C" void kernel_launch(void* const* d_in, const int* in_sizes, int n_in,
                              void* d_out, int out_size)
{
    const float* query  = (const float*)d_in[0];   // (4,4096,256)
    const float* refpts = (const float*)d_in[1];   // (4,4096,4,1)
    const float* flat   = (const float*)d_in[2];   // (4,7680,256)
    const int*   shapes = (const int*)  d_in[3];   // (4)
    const int*   start  = (const int*)  d_in[4];   // (4)
    const float* W_off  = (const float*)d_in[5];   // (256,128)
    const float* b_off  = (const float*)d_in[6];   // (128)
    const float* W_aw   = (const float*)d_in[7];   // (256,128)
    const float* b_aw   = (const float*)d_in[8];   // (128)
    const float* W_v    = (const float*)d_in[9];   // (256,256)
    const float* b_v    = (const float*)d_in[10];  // (256)
    const float* W_out  = (const float*)d_in[11];  // (256,256)
    const float* b_out  = (const float*)d_in[12];  // (256)
    float* out = (float*)d_out;                    // (4,4096,256)

    float *p_value, *p_off, *p_aw, *p_mid;
    cudaGetSymbolAddress((void**)&p_value, g_value);
    cudaGetSymbolAddress((void**)&p_off,   g_off);
    cudaGetSymbolAddress((void**)&p_aw,    g_aw);
    cudaGetSymbolAddress((void**)&p_mid,   g_mid);

    const int Mq = NB * LQ;     // 16384
    const int Mv = NB * S_TOT;  // 30720

    // value = flatten @ W_v + b_v          (30720 x 256 x 256)
    {
        dim3 grid(DM / 128, Mv / 128);
        sgemm_bias_kernel<<<grid, 256>>>(flat, W_v, b_v, p_value, Mv, DM, DM);
    }
    // off = query @ W_off + b_off          (16384 x 128 x 256)
    {
        dim3 grid(HLP / 128, Mq / 128);
        sgemm_bias_kernel<<<grid, 256>>>(query, W_off, b_off, p_off, Mq, HLP, DM);
    }
    // aw logits = query @ W_aw + b_aw      (16384 x 128 x 256)
    {
        dim3 grid(HLP / 128, Mq / 128);
        sgemm_bias_kernel<<<grid, 256>>>(query, W_aw, b_aw, p_aw, Mq, HLP, DM);
    }
    // sampling: softmax + gather + lerp -> g_mid
    msda_sample_kernel<<<Mq, 256>>>(refpts, shapes, start);

    // out = g_mid @ W_out + b_out          (16384 x 256 x 256)
    {
        dim3 grid(DM / 128, Mq / 128);
        sgemm_bias_kernel<<<grid, 256>>>(p_mid, W_out, b_out, out, Mq, DM, DM);
    }
}

// round 3
// speedup vs baseline: 2.2296x; 2.2296x over previous
#include <cuda_runtime.h>
#include <cuda_bf16.h>
#include <math.h>
#include <cstdint>

// ---------------- problem constants ----------------
#define NB      4
#define LQ      4096
#define DM      256
#define NH      8
#define NL      4
#define NP      4
#define DH      32
#define S_TOT   7680
#define HLP     128
#define MQ      (NB*LQ)     // 16384
#define MV      (NB*S_TOT)  // 30720

// ---------------- scratch (static device memory) ----------------
__device__ float g_value[MV * DM];     // value = flat @ W_v
__device__ float g_oa  [MQ * 256];     // cols 0:128 = off, 128:256 = aw logits
__device__ float g_mid [MQ * DM];      // sampled output (pre out-proj)
__device__ float g_BtV [256 * 256];    // W_v^T   [N,K] K-major
__device__ float g_BtOA[256 * 256];    // [W_off^T ; W_aw^T]
__device__ float g_BtO [256 * 256];    // W_out^T
__device__ float g_bOA [256];          // [b_off ; b_aw]

// ---------------- tf32 helpers ----------------
__device__ __forceinline__ uint32_t f2tf32(float f) {
    uint32_t r;
    asm("cvt.rna.tf32.f32 %0, %1;" : "=r"(r) : "f"(f));
    return r;
}

__device__ __forceinline__ void mma_tf32(float* c, const uint32_t* a,
                                         uint32_t b0, uint32_t b1) {
    asm volatile(
        "mma.sync.aligned.m16n8k8.row.col.f32.tf32.tf32.f32 "
        "{%0,%1,%2,%3}, {%4,%5,%6,%7}, {%8,%9}, {%0,%1,%2,%3};"
        : "+f"(c[0]), "+f"(c[1]), "+f"(c[2]), "+f"(c[3])
        : "r"(a[0]), "r"(a[1]), "r"(a[2]), "r"(a[3]), "r"(b0), "r"(b1));
}

// ---------------- tf32 mma.sync GEMM ----------------------------------------
// C[M,256](tiles 128x128) = A[M,256] @ Bt[256,256]^T + bias
// BK=32, double-buffered smem, row stride 36 words (conflict-free frag loads).
// 8 warps: warp tile 32(m) x 64(n) = 2x8 m16n8k8 mmas per k-step.
#define RS 36                      // smem row stride in words
#define BUFW (128 * RS)            // one matrix buffer: 4608 words
__global__ __launch_bounds__(256)
void mma_gemm_kernel(const float* __restrict__ A,
                     const float* __restrict__ Bt,
                     const float* __restrict__ bias,
                     float* __restrict__ C)
{
    extern __shared__ uint32_t smu[];  // 2 * 2 * BUFW words = 73728 B

    const int tid  = threadIdx.x;
    const int wid  = tid >> 5;
    const int lane = tid & 31;
    const int g8   = lane >> 2;   // group id 0..7
    const int t4   = lane & 3;    // thread in group
    const int block_row = blockIdx.y * 128;
    const int block_col = blockIdx.x * 128;
    const int warp_m = (wid >> 1) * 32;
    const int warp_n = (wid & 1) * 64;

    const float* Ag = A  + (long)block_row * 256;
    const float* Bg = Bt + (long)block_col * 256;

    float acc[2][8][4];
    #pragma unroll
    for (int im = 0; im < 2; im++)
        #pragma unroll
        for (int in_ = 0; in_ < 8; in_++)
            #pragma unroll
            for (int q = 0; q < 4; q++)
                acc[im][in_][q] = 0.0f;

    // copy mapping: 1024 float4 per matrix per iter; thread does 4 each
    const int cr[4] = { (tid + 0)   >> 3, (tid + 256) >> 3,
                        (tid + 512) >> 3, (tid + 768) >> 3 };
    const int cc = (tid & 7) * 4;

    float4 ra[4], rb[4];
    // prologue: load k-chunk 0
    #pragma unroll
    for (int j = 0; j < 4; j++) {
        ra[j] = *(const float4*)(Ag + (long)cr[j] * 256 + cc);
        rb[j] = *(const float4*)(Bg + (long)cr[j] * 256 + cc);
    }
    {
        uint32_t* Ad = smu;
        uint32_t* Bd = smu + BUFW;
        #pragma unroll
        for (int j = 0; j < 4; j++) {
            uint32_t* pa = Ad + cr[j] * RS + cc;
            pa[0] = f2tf32(ra[j].x); pa[1] = f2tf32(ra[j].y);
            pa[2] = f2tf32(ra[j].z); pa[3] = f2tf32(ra[j].w);
            uint32_t* pb = Bd + cr[j] * RS + cc;
            pb[0] = f2tf32(rb[j].x); pb[1] = f2tf32(rb[j].y);
            pb[2] = f2tf32(rb[j].z); pb[3] = f2tf32(rb[j].w);
        }
    }
    __syncthreads();

    for (int it = 0; it < 8; ++it) {
        const uint32_t* As_ = smu + (it & 1) * (2 * BUFW);
        const uint32_t* Bs_ = As_ + BUFW;

        if (it < 7) {  // prefetch next k-chunk into registers
            const int k0 = (it + 1) * 32;
            #pragma unroll
            for (int j = 0; j < 4; j++) {
                ra[j] = *(const float4*)(Ag + (long)cr[j] * 256 + k0 + cc);
                rb[j] = *(const float4*)(Bg + (long)cr[j] * 256 + k0 + cc);
            }
        }

        #pragma unroll
        for (int ks = 0; ks < 4; ks++) {
            const int kk = ks * 8 + t4;
            uint32_t af[2][4];
            #pragma unroll
            for (int im = 0; im < 2; im++) {
                const int m0 = warp_m + im * 16 + g8;
                af[im][0] = As_[ m0      * RS + kk    ];
                af[im][1] = As_[(m0 + 8) * RS + kk    ];
                af[im][2] = As_[ m0      * RS + kk + 4];
                af[im][3] = As_[(m0 + 8) * RS + kk + 4];
            }
            #pragma unroll
            for (int in_ = 0; in_ < 8; in_++) {
                const int n0 = warp_n + in_ * 8 + g8;
                uint32_t b0 = Bs_[n0 * RS + kk];
                uint32_t b1 = Bs_[n0 * RS + kk + 4];
                mma_tf32(acc[0][in_], af[0], b0, b1);
                mma_tf32(acc[1][in_], af[1], b0, b1);
            }
        }

        if (it < 7) {  // store prefetched chunk into the other buffer
            uint32_t* Ad = smu + ((it + 1) & 1) * (2 * BUFW);
            uint32_t* Bd = Ad + BUFW;
            #pragma unroll
            for (int j = 0; j < 4; j++) {
                uint32_t* pa = Ad + cr[j] * RS + cc;
                pa[0] = f2tf32(ra[j].x); pa[1] = f2tf32(ra[j].y);
                pa[2] = f2tf32(ra[j].z); pa[3] = f2tf32(ra[j].w);
                uint32_t* pb = Bd + cr[j] * RS + cc;
                pb[0] = f2tf32(rb[j].x); pb[1] = f2tf32(rb[j].y);
                pb[2] = f2tf32(rb[j].z); pb[3] = f2tf32(rb[j].w);
            }
            __syncthreads();
        }
    }

    // epilogue: float2 stores + bias
    #pragma unroll
    for (int im = 0; im < 2; im++) {
        const int r0 = block_row + warp_m + im * 16 + g8;
        #pragma unroll
        for (int in_ = 0; in_ < 8; in_++) {
            const int col = block_col + warp_n + in_ * 8 + 2 * t4;
            const float bx = bias[col], by = bias[col + 1];
            float2 o0 = make_float2(acc[im][in_][0] + bx, acc[im][in_][1] + by);
            float2 o1 = make_float2(acc[im][in_][2] + bx, acc[im][in_][3] + by);
            *(float2*)(C + (long)r0 * 256 + col)       = o0;
            *(float2*)(C + (long)(r0 + 8) * 256 + col) = o1;
        }
    }
}

// ---------------- weight transpose: Bt[rowoff+n, k] = W[k, n] ----------------
__global__ void transpose256(const float* __restrict__ W, float* __restrict__ Bt,
                             int N, int rowoff)
{
    __shared__ float t[32][33];
    int n0 = blockIdx.x * 32, k0 = blockIdx.y * 32;
    t[threadIdx.y][threadIdx.x] = W[(k0 + threadIdx.y) * N + n0 + threadIdx.x];
    __syncthreads();
    Bt[(long)(rowoff + n0 + threadIdx.y) * 256 + k0 + threadIdx.x] = t[threadIdx.x][threadIdx.y];
}

__global__ void concat_bias(const float* __restrict__ b0, const float* __restrict__ b1,
                            float* __restrict__ dst)
{
    int t = threadIdx.x;
    dst[t] = (t < 128) ? b0[t] : b1[t - 128];
}

// ---------------- sampling kernel -------------------------------------------
__global__ __launch_bounds__(256)
void msda_sample_kernel(const float* __restrict__ ref,
                        const int*   __restrict__ shapes,
                        const int*   __restrict__ start)
{
    const int nq   = blockIdx.x;
    const int n    = nq / LQ;
    const int m    = threadIdx.x >> 5;
    const int lane = threadIdx.x & 31;
    const int lp   = lane & 15;
    const int l    = lp >> 2;

    const int   Ti = shapes[l];
    const float Tf = (float)Ti;
    const int   st = start[l];

    const float offv  = g_oa[(long)nq * 256 +       m * 16 + lp];
    const float logit = g_oa[(long)nq * 256 + 128 + m * 16 + lp];
    const float r     = ref[(long)nq * NL + l];

    float x  = fminf(fmaxf(r * Tf + offv - 0.5f, 0.0f), Tf - 1.0f);
    float x0 = floorf(x);
    float w  = x - x0;
    int   i0 = (int)x0;
    int   i1 = min(i0 + 1, Ti - 1);
    int   g0 = (n * S_TOT + st + i0) * DM + m * DH;
    int   g1 = (n * S_TOT + st + i1) * DM + m * DH;

    float mx = logit;
    #pragma unroll
    for (int o = 8; o > 0; o >>= 1)
        mx = fmaxf(mx, __shfl_xor_sync(0xffffffffu, mx, o, 16));
    float e = expf(logit - mx);
    float ssum = e;
    #pragma unroll
    for (int o = 8; o > 0; o >>= 1)
        ssum += __shfl_xor_sync(0xffffffffu, ssum, o, 16);
    float aw = e / ssum;

    float acc = 0.0f;
    #pragma unroll
    for (int p = 0; p < 16; p++) {
        int   gg0 = __shfl_sync(0xffffffffu, g0, p);
        int   gg1 = __shfl_sync(0xffffffffu, g1, p);
        float ww  = __shfl_sync(0xffffffffu, w,  p);
        float aa  = __shfl_sync(0xffffffffu, aw, p);
        float v0 = g_value[gg0 + lane];
        float v1 = g_value[gg1 + lane];
        acc = fmaf(aa, fmaf(ww, v1 - v0, v0), acc);
    }

    g_mid[(long)nq * DM + m * DH + lane] = acc;
}

// ---------------- launch ------------------------------------------------------
extern "C" void kernel_launch(void* const* d_in, const int* in_sizes, int n_in,
                              void* d_out, int out_size)
{
    const float* query  = (const float*)d_in[0];
    const float* refpts = (const float*)d_in[1];
    const float* flat   = (const float*)d_in[2];
    const int*   shapes = (const int*)  d_in[3];
    const int*   start  = (const int*)  d_in[4];
    const float* W_off  = (const float*)d_in[5];
    const float* b_off  = (const float*)d_in[6];
    const float* W_aw   = (const float*)d_in[7];
    const float* b_aw   = (const float*)d_in[8];
    const float* W_v    = (const float*)d_in[9];
    const float* b_v    = (const float*)d_in[10];
    const float* W_out  = (const float*)d_in[11];
    const float* b_out  = (const float*)d_in[12];
    float* out = (float*)d_out;

    float *p_value, *p_oa, *p_mid, *p_BtV, *p_BtOA, *p_BtO, *p_bOA;
    cudaGetSymbolAddress((void**)&p_value, g_value);
    cudaGetSymbolAddress((void**)&p_oa,    g_oa);
    cudaGetSymbolAddress((void**)&p_mid,   g_mid);
    cudaGetSymbolAddress((void**)&p_BtV,   g_BtV);
    cudaGetSymbolAddress((void**)&p_BtOA,  g_BtOA);
    cudaGetSymbolAddress((void**)&p_BtO,   g_BtO);
    cudaGetSymbolAddress((void**)&p_bOA,   g_bOA);

    const int smem_bytes = 4 * BUFW * 4;   // 73728
    static bool attr_set = false;
    if (!attr_set) {
        cudaFuncSetAttribute(mma_gemm_kernel,
                             cudaFuncAttributeMaxDynamicSharedMemorySize, smem_bytes);
        attr_set = true;
    }

    dim3 tb(32, 32);
    transpose256<<<dim3(8, 8), tb>>>(W_v,   p_BtV,  256, 0);
    transpose256<<<dim3(4, 8), tb>>>(W_off, p_BtOA, 128, 0);
    transpose256<<<dim3(4, 8), tb>>>(W_aw,  p_BtOA, 128, 128);
    transpose256<<<dim3(8, 8), tb>>>(W_out, p_BtO,  256, 0);
    concat_bias<<<1, 256>>>(b_off, b_aw, p_bOA);

    // value = flat @ W_v + b_v            (30720 x 256 x 256)
    mma_gemm_kernel<<<dim3(2, MV / 128), 256, smem_bytes>>>(flat, p_BtV, b_v, p_value);
    // [off|aw] = query @ [W_off|W_aw]     (16384 x 256 x 256, fused)
    mma_gemm_kernel<<<dim3(2, MQ / 128), 256, smem_bytes>>>(query, p_BtOA, p_bOA, p_oa);
    // sampling
    msda_sample_kernel<<<MQ, 256>>>(refpts, shapes, start);
    // out = mid @ W_out + b_out           (16384 x 256 x 256)
    mma_gemm_kernel<<<dim3(2, MQ / 128), 256, smem_bytes>>>(p_mid, p_BtO, b_out, out);
}

// round 4
// speedup vs baseline: 2.9833x; 1.3380x over previous
#include <cuda_runtime.h>
#include <cuda_bf16.h>
#include <math.h>
#include <cstdint>

// ---------------- problem constants ----------------
#define NB      4
#define LQ      4096
#define DM      256
#define NH      8
#define NL      4
#define NP      4
#define DH      32
#define S_TOT   7680
#define HLP     128
#define MQ      (NB*LQ)     // 16384
#define MV      (NB*S_TOT)  // 30720

// ---------------- scratch (static device memory) ----------------
__device__ float g_value[MV * DM];     // value = flat @ W_v
__device__ float g_oa  [MQ * 256];     // cols 0:128 = off, 128:256 = aw logits
__device__ float g_mid [MQ * DM];      // sampled output (pre out-proj)
__device__ float g_BtV [256 * 256];    // W_v^T   [N,K] K-major
__device__ float g_BtOA[256 * 256];    // [W_off^T ; W_aw^T]
__device__ float g_BtO [256 * 256];    // W_out^T
__device__ float g_bOA [256];          // [b_off ; b_aw]

// ---------------- tf32 helpers ----------------
__device__ __forceinline__ uint32_t f2tf32(float f) {
    uint32_t r;
    asm("cvt.rna.tf32.f32 %0, %1;" : "=r"(r) : "f"(f));
    return r;
}

__device__ __forceinline__ void mma_tf32(float* c, const uint32_t* a,
                                         uint32_t b0, uint32_t b1) {
    asm volatile(
        "mma.sync.aligned.m16n8k8.row.col.f32.tf32.tf32.f32 "
        "{%0,%1,%2,%3}, {%4,%5,%6,%7}, {%8,%9}, {%0,%1,%2,%3};"
        : "+f"(c[0]), "+f"(c[1]), "+f"(c[2]), "+f"(c[3])
        : "r"(a[0]), "r"(a[1]), "r"(a[2]), "r"(a[3]), "r"(b0), "r"(b1));
}

// ---------------- tf32 mma.sync GEMM (two independent GEMMs fused) -----------
// blockIdx.y < rows0 -> GEMM0 (A0,B0,bias0,C0); else GEMM1. N=256, K=256 both.
#define RS 36
#define BUFW (128 * RS)
__global__ __launch_bounds__(256)
void mma_gemm_kernel(const float* __restrict__ A0, const float* __restrict__ B0,
                     const float* __restrict__ bias0, float* __restrict__ C0,
                     int rows0,
                     const float* __restrict__ A1, const float* __restrict__ B1,
                     const float* __restrict__ bias1, float* __restrict__ C1)
{
    extern __shared__ uint32_t smu[];  // 73728 B

    const float* A;  const float* Bt;  const float* bias;  float* C;
    int block_row;
    if ((int)blockIdx.y < rows0) {
        A = A0; Bt = B0; bias = bias0; C = C0; block_row = blockIdx.y * 128;
    } else {
        A = A1; Bt = B1; bias = bias1; C = C1; block_row = (blockIdx.y - rows0) * 128;
    }

    const int tid  = threadIdx.x;
    const int wid  = tid >> 5;
    const int lane = tid & 31;
    const int g8   = lane >> 2;
    const int t4   = lane & 3;
    const int block_col = blockIdx.x * 128;
    const int warp_m = (wid >> 1) * 32;
    const int warp_n = (wid & 1) * 64;

    const float* Ag = A  + (long)block_row * 256;
    const float* Bg = Bt + (long)block_col * 256;

    float acc[2][8][4];
    #pragma unroll
    for (int im = 0; im < 2; im++)
        #pragma unroll
        for (int in_ = 0; in_ < 8; in_++)
            #pragma unroll
            for (int q = 0; q < 4; q++)
                acc[im][in_][q] = 0.0f;

    const int cr[4] = { (tid + 0)   >> 3, (tid + 256) >> 3,
                        (tid + 512) >> 3, (tid + 768) >> 3 };
    const int cc = (tid & 7) * 4;

    float4 ra[4], rb[4];
    #pragma unroll
    for (int j = 0; j < 4; j++) {
        ra[j] = *(const float4*)(Ag + (long)cr[j] * 256 + cc);
        rb[j] = *(const float4*)(Bg + (long)cr[j] * 256 + cc);
    }
    {
        uint32_t* Ad = smu;
        uint32_t* Bd = smu + BUFW;
        #pragma unroll
        for (int j = 0; j < 4; j++) {
            uint32_t* pa = Ad + cr[j] * RS + cc;
            pa[0] = f2tf32(ra[j].x); pa[1] = f2tf32(ra[j].y);
            pa[2] = f2tf32(ra[j].z); pa[3] = f2tf32(ra[j].w);
            uint32_t* pb = Bd + cr[j] * RS + cc;
            pb[0] = f2tf32(rb[j].x); pb[1] = f2tf32(rb[j].y);
            pb[2] = f2tf32(rb[j].z); pb[3] = f2tf32(rb[j].w);
        }
    }
    __syncthreads();

    for (int it = 0; it < 8; ++it) {
        const uint32_t* As_ = smu + (it & 1) * (2 * BUFW);
        const uint32_t* Bs_ = As_ + BUFW;

        if (it < 7) {
            const int k0 = (it + 1) * 32;
            #pragma unroll
            for (int j = 0; j < 4; j++) {
                ra[j] = *(const float4*)(Ag + (long)cr[j] * 256 + k0 + cc);
                rb[j] = *(const float4*)(Bg + (long)cr[j] * 256 + k0 + cc);
            }
        }

        #pragma unroll
        for (int ks = 0; ks < 4; ks++) {
            const int kk = ks * 8 + t4;
            uint32_t af[2][4];
            #pragma unroll
            for (int im = 0; im < 2; im++) {
                const int m0 = warp_m + im * 16 + g8;
                af[im][0] = As_[ m0      * RS + kk    ];
                af[im][1] = As_[(m0 + 8) * RS + kk    ];
                af[im][2] = As_[ m0      * RS + kk + 4];
                af[im][3] = As_[(m0 + 8) * RS + kk + 4];
            }
            #pragma unroll
            for (int in_ = 0; in_ < 8; in_++) {
                const int n0 = warp_n + in_ * 8 + g8;
                uint32_t b0 = Bs_[n0 * RS + kk];
                uint32_t b1 = Bs_[n0 * RS + kk + 4];
                mma_tf32(acc[0][in_], af[0], b0, b1);
                mma_tf32(acc[1][in_], af[1], b0, b1);
            }
        }

        if (it < 7) {
            uint32_t* Ad = smu + ((it + 1) & 1) * (2 * BUFW);
            uint32_t* Bd = Ad + BUFW;
            #pragma unroll
            for (int j = 0; j < 4; j++) {
                uint32_t* pa = Ad + cr[j] * RS + cc;
                pa[0] = f2tf32(ra[j].x); pa[1] = f2tf32(ra[j].y);
                pa[2] = f2tf32(ra[j].z); pa[3] = f2tf32(ra[j].w);
                uint32_t* pb = Bd + cr[j] * RS + cc;
                pb[0] = f2tf32(rb[j].x); pb[1] = f2tf32(rb[j].y);
                pb[2] = f2tf32(rb[j].z); pb[3] = f2tf32(rb[j].w);
            }
            __syncthreads();
        }
    }

    #pragma unroll
    for (int im = 0; im < 2; im++) {
        const int r0 = block_row + warp_m + im * 16 + g8;
        #pragma unroll
        for (int in_ = 0; in_ < 8; in_++) {
            const int col = block_col + warp_n + in_ * 8 + 2 * t4;
            const float bx = bias[col], by = bias[col + 1];
            float2 o0 = make_float2(acc[im][in_][0] + bx, acc[im][in_][1] + by);
            float2 o1 = make_float2(acc[im][in_][2] + bx, acc[im][in_][3] + by);
            *(float2*)(C + (long)r0 * 256 + col)       = o0;
            *(float2*)(C + (long)(r0 + 8) * 256 + col) = o1;
        }
    }
}

// ---------------- fused prep: 4 transposes + bias concat ---------------------
// blocks 0..63: W_v -> g_BtV | 64..95: W_off -> g_BtOA[0:128]
// 96..127: W_aw -> g_BtOA[128:256] | 128..191: W_out -> g_BtO | 192: bias
__global__ void prep_kernel(const float* __restrict__ W_v,
                            const float* __restrict__ W_off,
                            const float* __restrict__ W_aw,
                            const float* __restrict__ W_out,
                            const float* __restrict__ b_off,
                            const float* __restrict__ b_aw)
{
    const int b = blockIdx.x;
    if (b == 192) {
        int t = threadIdx.y * 32 + threadIdx.x;
        if (t < 256) g_bOA[t] = (t < 128) ? b_off[t] : b_aw[t - 128];
        return;
    }
    const float* W; float* Bt; int N, rowoff, local;
    if (b < 64)       { W = W_v;   Bt = g_BtV;  N = 256; rowoff = 0;   local = b; }
    else if (b < 96)  { W = W_off; Bt = g_BtOA; N = 128; rowoff = 0;   local = b - 64; }
    else if (b < 128) { W = W_aw;  Bt = g_BtOA; N = 128; rowoff = 128; local = b - 96; }
    else              { W = W_out; Bt = g_BtO;  N = 256; rowoff = 0;   local = b - 128; }
    const int nx = N / 32;
    const int n0 = (local % nx) * 32;
    const int k0 = (local / nx) * 32;

    __shared__ float t[32][33];
    t[threadIdx.y][threadIdx.x] = W[(k0 + threadIdx.y) * N + n0 + threadIdx.x];
    __syncthreads();
    Bt[(long)(rowoff + n0 + threadIdx.y) * 256 + k0 + threadIdx.x] = t[threadIdx.x][threadIdx.y];
}

// ---------------- sampling kernel v2 ------------------------------------------
// Block = 1 query, 8 warps = 8 heads. Phase 1: lanes 0..15 compute per-point
// {g0,g1,w,aw} -> smem float4 (warp-private). Phase 2: 4 groups x 8 lanes do
// float4 gathers (LDG.128), zero shuffles in the loop; 2-step butterfly reduce.
__global__ __launch_bounds__(256)
void msda_sample_kernel(const float* __restrict__ ref,
                        const int*   __restrict__ shapes,
                        const int*   __restrict__ start)
{
    __shared__ float4 sp[NH][16];   // per-head point params

    const int nq   = blockIdx.x;
    const int n    = nq / LQ;
    const int m    = threadIdx.x >> 5;
    const int lane = threadIdx.x & 31;
    const int lp   = lane & 15;
    const int l    = lp >> 2;

    // ---- phase 1: positions + softmax (lanes 16-31 duplicate lanes 0-15) ----
    {
        const int   Ti = shapes[l];
        const float Tf = (float)Ti;
        const int   st = start[l];

        const float offv  = g_oa[(long)nq * 256 +       m * 16 + lp];
        const float logit = g_oa[(long)nq * 256 + 128 + m * 16 + lp];
        const float r     = ref[(long)nq * NL + l];

        float x  = fminf(fmaxf(r * Tf + offv - 0.5f, 0.0f), Tf - 1.0f);
        float x0 = floorf(x);
        float w  = x - x0;
        int   i0 = (int)x0;
        int   i1 = min(i0 + 1, Ti - 1);
        int   g0 = (n * S_TOT + st + i0) * DM + m * DH;
        int   g1 = (n * S_TOT + st + i1) * DM + m * DH;

        float mx = logit;
        #pragma unroll
        for (int o = 8; o > 0; o >>= 1)
            mx = fmaxf(mx, __shfl_xor_sync(0xffffffffu, mx, o, 16));
        float e = expf(logit - mx);
        float ssum = e;
        #pragma unroll
        for (int o = 8; o > 0; o >>= 1)
            ssum += __shfl_xor_sync(0xffffffffu, ssum, o, 16);
        float aw = e / ssum;

        if (lane < 16)
            sp[m][lp] = make_float4(__int_as_float(g0), __int_as_float(g1), w, aw);
    }
    __syncwarp();

    // ---- phase 2: gathers. group g = lane>>3 (4 pts/iter), c = lane&7 -------
    const int g = lane >> 3;
    const int c = lane & 7;
    float4 acc = make_float4(0.f, 0.f, 0.f, 0.f);
    #pragma unroll
    for (int t = 0; t < 4; t++) {
        float4 pr = sp[m][t * 4 + g];
        int   ig0 = __float_as_int(pr.x);
        int   ig1 = __float_as_int(pr.y);
        float w   = pr.z;
        float aw  = pr.w;
        float4 v0 = *(const float4*)(g_value + ig0 + c * 4);
        float4 v1 = *(const float4*)(g_value + ig1 + c * 4);
        acc.x = fmaf(aw, fmaf(w, v1.x - v0.x, v0.x), acc.x);
        acc.y = fmaf(aw, fmaf(w, v1.y - v0.y, v0.y), acc.y);
        acc.z = fmaf(aw, fmaf(w, v1.z - v0.z, v0.z), acc.z);
        acc.w = fmaf(aw, fmaf(w, v1.w - v0.w, v0.w), acc.w);
    }
    // reduce over 4 groups (lanes xor 8, 16)
    #pragma unroll
    for (int o = 8; o <= 16; o <<= 1) {
        acc.x += __shfl_xor_sync(0xffffffffu, acc.x, o);
        acc.y += __shfl_xor_sync(0xffffffffu, acc.y, o);
        acc.z += __shfl_xor_sync(0xffffffffu, acc.z, o);
        acc.w += __shfl_xor_sync(0xffffffffu, acc.w, o);
    }
    if (lane < 8)
        *(float4*)(g_mid + (long)nq * DM + m * DH + c * 4) = acc;
}

// ---------------- launch ------------------------------------------------------
extern "C" void kernel_launch(void* const* d_in, const int* in_sizes, int n_in,
                              void* d_out, int out_size)
{
    const float* query  = (const float*)d_in[0];
    const float* refpts = (const float*)d_in[1];
    const float* flat   = (const float*)d_in[2];
    const int*   shapes = (const int*)  d_in[3];
    const int*   start  = (const int*)  d_in[4];
    const float* W_off  = (const float*)d_in[5];
    const float* b_off  = (const float*)d_in[6];
    const float* W_aw   = (const float*)d_in[7];
    const float* b_aw   = (const float*)d_in[8];
    const float* W_v    = (const float*)d_in[9];
    const float* b_v    = (const float*)d_in[10];
    const float* W_out  = (const float*)d_in[11];
    const float* b_out  = (const float*)d_in[12];
    float* out = (float*)d_out;

    float *p_value, *p_oa, *p_mid, *p_BtV, *p_BtOA, *p_BtO, *p_bOA;
    cudaGetSymbolAddress((void**)&p_value, g_value);
    cudaGetSymbolAddress((void**)&p_oa,    g_oa);
    cudaGetSymbolAddress((void**)&p_mid,   g_mid);
    cudaGetSymbolAddress((void**)&p_BtV,   g_BtV);
    cudaGetSymbolAddress((void**)&p_BtOA,  g_BtOA);
    cudaGetSymbolAddress((void**)&p_BtO,   g_BtO);
    cudaGetSymbolAddress((void**)&p_bOA,   g_bOA);

    const int smem_bytes = 4 * BUFW * 4;   // 73728
    static bool attr_set = false;
    if (!attr_set) {
        cudaFuncSetAttribute(mma_gemm_kernel,
                             cudaFuncAttributeMaxDynamicSharedMemorySize, smem_bytes);
        attr_set = true;
    }

    // prep: all weight transposes + bias concat (1 launch)
    prep_kernel<<<193, dim3(32, 32)>>>(W_v, W_off, W_aw, W_out, b_off, b_aw);

    // fused: value = flat@W_v + b_v (240 row-tiles) and [off|aw] = query@BtOA (128)
    mma_gemm_kernel<<<dim3(2, MV / 128 + MQ / 128), 256, smem_bytes>>>(
        flat, p_BtV, b_v, p_value, MV / 128,
        query, p_BtOA, p_bOA, p_oa);

    // sampling
    msda_sample_kernel<<<MQ, 256>>>(refpts, shapes, start);

    // out = mid @ W_out + b_out
    mma_gemm_kernel<<<dim3(2, MQ / 128), 256, smem_bytes>>>(
        p_mid, p_BtO, b_out, out, MQ / 128,
        p_mid, p_BtO, b_out, out);
}